// round 4
// baseline (speedup 1.0000x reference)
#include <cuda_runtime.h>
#include <math.h>
#include <stdint.h>

// Problem constants (fixed shapes from setup_inputs)
#define BB 8
#define CC 5
#define HH 768
#define WW 768
#define HW (HH*WW)
#define NPIX (BB*HW)          // 4,718,592
#define NTC 4

#define EPSF 1e-7f
#define ONEMF ((float)(1.0 - 1e-7))

// strips for local CCL
#define SH 8
#define SPIX (SH*WW)              // 6144
#define STRIPS_PER_IMG (HH/SH)    // 96
#define NSTRIP (BB*STRIPS_PER_IMG)// 768
#define NBOUND (BB*(STRIPS_PER_IMG-1))    // 760 strip boundaries
#define NEDGE (NBOUND*WW)                 // 583,680
#define SLOTS 1536                        // border slots per strip (2*WW)
#define NSLOT (NSTRIP*SLOTS)              // 1,179,648  (< 2^23)

// ---------------- static device scratch ----------------
__device__ unsigned char g_pm[NPIX];        // argmax class per pixel
__device__ int           g_uf[NSLOT];       // compact global UF over border slots (4.7MB, L2-resident)
__device__ int           g_btop[NSTRIP*WW]; // packed rep-slot of top-row pixels (-1 = bg)
__device__ int           g_bbot[NSTRIP*WW]; // packed rep-slot of bottom-row pixels
__device__ double        g_acc[4][20];      // [stat][cell]: 0=cnt 1=spho 2=slog 3=sl1p
__device__ int           g_lroots[4];       // local component counts per class 1..4
__device__ int           g_merged[4];       // successful cross-strip unions per class

// ---------------- K0: zero accumulators ----------------
__global__ void k_zero() {
    int t = threadIdx.x;
    if (t < 80) ((double*)g_acc)[t] = 0.0;
    if (t < 4) { g_lroots[t] = 0; g_merged[t] = 0; }
}

__global__ void k_nop() {}

// ---------------- K1: argmax + joint stats (per-lane slabs, no atomics) ----------------
// grid (96, 8), block 128. Each block: 1536 vec4 of one image.
__global__ void __launch_bounds__(128) k_stats(const float* __restrict__ pred,
                                               const int*   __restrict__ tmask) {
    __shared__ float slab[4][4][20][32];   // [warp][stat][cell][lane] — bank-conflict free
    const int tid  = threadIdx.x;
    const int warp = tid >> 5, lane = tid & 31;
    for (int k = tid; k < 4*4*20*32; k += 128) ((float*)slab)[k] = 0.f;
    __syncthreads();

    const int img = blockIdx.y;
    const float* pb = pred + (size_t)img * CC * HW;
    const int4*  tb = (const int4*)(tmask + (size_t)img * HW);
    uchar4* pmb = (uchar4*)g_pm + (size_t)img * (HW/4);
    float* my = &slab[warp][0][0][lane];
    const int start = blockIdx.x * 1536;

    #pragma unroll 2
    for (int it = 0; it < 12; ++it) {
        int v = start + it * 128 + tid;       // vec4 index within image
        int j = v * 4;
        float4 c0 = *(const float4*)(pb + j);
        float4 c1 = *(const float4*)(pb + HW + j);
        float4 c2 = *(const float4*)(pb + 2*HW + j);
        float4 c3 = *(const float4*)(pb + 3*HW + j);
        float4 c4 = *(const float4*)(pb + 4*HW + j);
        int4  tv  = tb[v];

        float A0[4] = {c0.x, c0.y, c0.z, c0.w};
        float A1[4] = {c1.x, c1.y, c1.z, c1.w};
        float A2[4] = {c2.x, c2.y, c2.z, c2.w};
        float A3[4] = {c3.x, c3.y, c3.z, c3.w};
        float A4[4] = {c4.x, c4.y, c4.z, c4.w};
        int tvv[4] = {tv.x, tv.y, tv.z, tv.w};
        unsigned char bcs[4];

        #pragma unroll
        for (int e = 0; e < 4; e++) {
            float best = A0[e]; int bc = 0;
            if (A1[e] > best) { best = A1[e]; bc = 1; }
            if (A2[e] > best) { best = A2[e]; bc = 2; }
            if (A3[e] > best) { best = A3[e]; bc = 3; }
            if (A4[e] > best) { best = A4[e]; bc = 4; }
            bcs[e] = (unsigned char)bc;

            int t = tvv[e]; t = t < 0 ? 0 : (t > 3 ? 3 : t);
            int cell = t * 5 + bc;
            float q  = bc ? best : 0.0f;
            float qc = fminf(fmaxf(q, EPSF), ONEMF);
            float lg = __logf(qc);
            float l1 = __logf(1.0f - qc);
            float* p = my + cell * 32;        // stat stride = 20*32 = 640 floats
            p[0]    += 1.0f;
            p[640]  += q;
            p[1280] += lg;
            p[1920] += l1;
        }
        pmb[v] = make_uchar4(bcs[0], bcs[1], bcs[2], bcs[3]);
    }
    __syncthreads();

    if (tid < 80) {
        int s = tid / 20, c = tid % 20;
        double acc = 0.0;
        #pragma unroll
        for (int w = 0; w < 4; w++)
            for (int l = 0; l < 32; l++) acc += (double)slab[w][s][c][l];
        atomicAdd(&g_acc[s][c], acc);
    }
}

// ---------------- shared-memory union-find ----------------
__device__ __forceinline__ int find_s(int* lab, int x) {
    int r = x, l = lab[r];
    while (l != r) { r = l; l = lab[r]; }
    int c = x;
    while (c != r) { int n = lab[c]; if (n == r) break; lab[c] = r; c = n; }
    return r;
}
__device__ __forceinline__ void union_s(int* lab, int a, int b) {
    while (true) {
        a = find_s(lab, a); b = find_s(lab, b);
        if (a == b) return;
        if (a < b) { int t = a; a = b; b = t; }
        int old = atomicCAS(&lab[a], a, b);
        if (old == a) return;
        a = old;
    }
}

// ---------------- K2: per-strip local CCL + root counts + compact border export ----------------
__global__ void __launch_bounds__(256) k_ccl() {
    __shared__ int lab[SPIX];              // 24KB (repurposed as minpos later)
    __shared__ unsigned char pm[SPIX];     // 6KB
    __shared__ int rootof[SLOTS];          // 6KB: local root of each border pixel
    __shared__ int rc[4];
    const int tid = threadIdx.x;
    const int strip = blockIdx.x;
    const int base = strip * SPIX;

    for (int v = tid; v < SPIX/16; v += 256)
        ((int4*)pm)[v] = ((const int4*)(g_pm + base))[v];
    for (int j = tid; j < SPIX; j += 256) lab[j] = j;
    if (tid < 4) rc[tid] = 0;
    __syncthreads();

    // local 4-connected union-find within the strip
    for (int j = tid; j < SPIX; j += 256) {
        int c = pm[j];
        if (!c) continue;
        int w = j - (j / WW) * WW;
        if (w       && pm[j - 1]  == c) union_s(lab, j, j - 1);
        if (j >= WW && pm[j - WW] == c) union_s(lab, j, j - WW);
    }
    __syncthreads();

    // root count per class via warp ballots
    for (int j = tid; j < SPIX; j += 256) {
        int c = pm[j];
        int cls = (c && lab[j] == j) ? c : 0;
        #pragma unroll
        for (int k = 1; k <= 4; k++) {
            unsigned m = __ballot_sync(0xFFFFFFFFu, cls == k);
            if ((tid & 31) == 0 && m) atomicAdd(&rc[k - 1], __popc(m));
        }
    }
    // resolve roots of border pixels BEFORE repurposing lab
    for (int bp = tid; bp < SLOTS; bp += 256) {
        int j = (bp < WW) ? bp : (SPIX - WW) + (bp - WW);
        rootof[bp] = pm[j] ? find_s(lab, j) : -1;
    }
    __syncthreads();
    // repurpose lab as minpos[root]
    for (int j = tid; j < SPIX; j += 256) lab[j] = 0x7FFFFFFF;
    __syncthreads();
    for (int bp = tid; bp < SLOTS; bp += 256) {
        int r = rootof[bp];
        if (r >= 0) atomicMin(&lab[r], bp);
    }
    __syncthreads();
    // export: each border pixel -> slot; link slot to representative slot (min bp of same root)
    for (int bp = tid; bp < SLOTS; bp += 256) {
        int j = (bp < WW) ? bp : (SPIX - WW) + (bp - WW);
        int c = pm[j];
        int slot = strip * SLOTS + bp;
        int link = slot, val = -1;
        if (c) {
            int rep = lab[rootof[bp]];
            link = strip * SLOTS + rep;
            val = link | (c << 23);
        }
        g_uf[slot] = link;                                   // coalesced
        if (bp < WW) g_btop[strip * WW + bp] = val;
        else         g_bbot[strip * WW + (bp - WW)] = val;
    }
    __syncthreads();
    if (tid < 4) atomicAdd(&g_lroots[tid], rc[tid]);
}

// ---------------- compact global union-find ----------------
__device__ __forceinline__ int uf_find_g(int x) {
    int r = x, l = g_uf[r];
    while (l != r) { r = l; l = g_uf[r]; }
    int c = x;
    while (c != r) { int n = g_uf[c]; if (n == r) break; g_uf[c] = r; c = n; }
    return r;
}
__device__ __forceinline__ bool uf_union_g(int a, int b) {
    while (true) {
        a = uf_find_g(a); b = uf_find_g(b);
        if (a == b) return false;
        if (a < b) { int t = a; a = b; b = t; }
        int old = atomicCAS(&g_uf[a], a, b);
        if (old == a) return true;
        a = old;
    }
}

// ---------------- K3: cross-strip border merge (deduped, compact table) ----------------
__global__ void __launch_bounds__(256) k_border() {
    int e = blockIdx.x * blockDim.x + threadIdx.x;
    int lane = threadIdx.x & 31;
    int myclass = 0;
    int va = -1, vb = -1;
    if (e < NEDGE) {
        int w  = e % WW;
        int bi = e / WW;                       // 0..759
        int img = bi / (STRIPS_PER_IMG - 1);
        int brow = bi - img * (STRIPS_PER_IMG - 1);
        int s = img * STRIPS_PER_IMG + brow;
        va = g_bbot[s * WW + w];
        vb = g_btop[(s + 1) * WW + w];
    }
    int pva = __shfl_up_sync(0xFFFFFFFFu, va, 1);
    int pvb = __shfl_up_sync(0xFFFFFFFFu, vb, 1);
    bool dup = (lane > 0) && (va == pva) && (vb == pvb);   // adjacent-run dedup (idempotent)
    if (e < NEDGE && !dup && (va | vb) >= 0) {
        int ca = va >> 23;
        if (ca == (vb >> 23)) {
            if (uf_union_g(va & 0x7FFFFF, vb & 0x7FFFFF)) myclass = ca;
        }
    }
    #pragma unroll
    for (int k = 1; k <= 4; k++) {
        unsigned m = __ballot_sync(0xFFFFFFFFu, myclass == k);
        if (lane == 0 && m) atomicAdd(&g_merged[k - 1], __popc(m));
    }
}

// ---------------- K4: scalar assembly ----------------
__global__ void k_final(float* __restrict__ out) {
    if (threadIdx.x != 0 || blockIdx.x != 0) return;

    long long cnt[4][5];
    double spho[4][5], slog[4][5], slog1p[4][5];
    for (int t = 0; t < 4; t++)
        for (int c = 0; c < 5; c++) {
            int k = t * 5 + c;
            cnt[t][c]    = (long long)(g_acc[0][k] + 0.5);
            spho[t][c]   = g_acc[1][k];
            slog[t][c]   = g_acc[2][k];
            slog1p[t][c] = g_acc[3][k];
        }
    long long cpm[5] = {0,0,0,0,0};
    long long ctm[4] = {0,0,0,0};
    for (int t = 0; t < 4; t++)
        for (int c = 0; c < 5; c++) { cpm[c] += cnt[t][c]; ctm[t] += cnt[t][c]; }

    // exact-f32 emulation of ph class values
    float phv[5] = {0.f,0.f,0.f,0.f,0.f};
    int last_i = 1;
    for (int v = 1; v < 5; v++) {
        bool present = (cpm[v] > 0);
        int has_bg = (cpm[v] < (long long)NPIX) ? 1 : 0;
        int nc = g_lroots[v - 1] - g_merged[v - 1];
        int wrapped = (int)((unsigned int)nc * (unsigned int)last_i);
        float s = (float)wrapped;
        if (present) {
            #pragma unroll
            for (int c = 0; c < 5; c++) {
                float ind = (c == v) ? 1.0f : 0.0f;
                float inc = ind + s;
                phv[c] = phv[c] + inc;
            }
            last_i += nc + has_bg;
        }
    }

    const double Nd = (double)NPIX;
    // Precomputed (double-exact) log constants:
    //  dEPS  = (double)(float)1e-7  = 1.0000000116860974e-7
    //  dONEM = (double)(float)(1-1e-7) = 1 - 2^-23
    const double LOG_EPS     = -16.1180956392722239;   // log(dEPS)
    const double LOG_ONEM    = -1.1920929665620861e-07;// log(1 - 2^-23)
    const double LOG1P_NEPS  = -1.0000000616860977e-07;// log1p(-dEPS)
    const double LOG1P_NONEM = -15.9423851528787421;   // log(2^-23) = -23*ln2

    double res = 0.0;

    { // term 0: bce_dice(pm==0, tm==0)
        long long n00 = cnt[0][0];
        long long np0 = cpm[0];
        long long nt0 = ctm[0];
        double bsum = (double)n00 * LOG_ONEM
                    + (double)(nt0 - n00) * LOG_EPS
                    + (double)(np0 - n00) * LOG1P_NONEM
                    + (double)((long long)NPIX - nt0 - np0 + n00) * LOG1P_NEPS;
        double bce = -bsum / Nd;
        double dice = 1.0 - (2.0 * (double)n00 + 1.0) / ((double)np0 + (double)nt0 + 1.0);
        res += bce + dice;
    }

    for (int t = 1; t < NTC; t++) {
        long long nt = ctm[t];
        if (nt <= 0) continue;

        int ord[5] = {0,1,2,3,4};
        for (int i = 1; i < 5; i++) {
            int o = ord[i]; float v = phv[o]; int j = i - 1;
            while (j >= 0 && phv[ord[j]] > v) { ord[j+1] = ord[j]; j--; }
            ord[j+1] = o;
        }
        long long kk = (nt - 1) / 2;
        float med = phv[ord[4]];
        long long cum = 0;
        for (int j = 0; j < 5; j++) {
            cum += cnt[t][ord[j]];
            if (cum > kk) { med = phv[ord[j]]; break; }
        }
        bool sel[5];
        #pragma unroll
        for (int c = 0; c < 5; c++) sel[c] = (phv[c] == med);

        double bsum = 0.0, sum_p = 0.0, inter = 0.0, extra_sum = 0.0;
        for (int c = 0; c < 5; c++) {
            if (sel[c]) {
                bsum += slog[t][c];
                inter += spho[t][c];
                for (int tt = 0; tt < 4; tt++) {
                    sum_p += spho[tt][c];
                    if (tt != t) bsum += slog1p[tt][c];
                }
            } else {
                bsum += (double)cnt[t][c] * LOG_EPS;
                extra_sum += spho[t][c];
                for (int tt = 0; tt < 4; tt++)
                    if (tt != t) bsum += (double)cnt[tt][c] * LOG1P_NEPS;
            }
        }
        double bce = -bsum / Nd;
        double dice = 1.0 - (2.0 * inter + 1.0) / (sum_p + (double)nt + 1.0);
        double extra = extra_sum / (double)(nt > 0 ? nt : 1);
        res += bce + dice + extra;
    }

    int nu = 0;
    for (int t = 0; t < NTC; t++) if (ctm[t] > 0) nu++;
    out[0] = (float)(res / (double)(2 * nu + 1));
}

// ---------------- launch ----------------
extern "C" void kernel_launch(void* const* d_in, const int* in_sizes, int n_in,
                              void* d_out, int out_size) {
    const float* pred = (const float*)d_in[0];
    const int*   tm   = (const int*)d_in[1];
    float* out = (float*)d_out;
    (void)in_sizes; (void)n_in; (void)out_size;

    k_zero<<<1, 96>>>();                       // slot 1
    k_stats<<<dim3(96, 8), 128>>>(pred, tm);   // slot 2
    k_nop<<<1, 32>>>();                        // slot 3 (positions k_ccl at profiled slot 4)
    k_ccl<<<NSTRIP, 256>>>();                  // slot 4 — profiled
    k_border<<<(NEDGE + 255) / 256, 256>>>();  // slot 5
    k_final<<<1, 1>>>(out);                    // slot 6
}

// round 5
// speedup vs baseline: 1.2229x; 1.2229x over previous
#include <cuda_runtime.h>
#include <math.h>
#include <stdint.h>

// Problem constants (fixed shapes from setup_inputs)
#define BB 8
#define CC 5
#define HH 768
#define WW 768
#define HW (HH*WW)
#define NPIX (BB*HW)          // 4,718,592
#define NTC 4

#define EPSF 1e-7f
#define ONEMF ((float)(1.0 - 1e-7))

// strips for local CCL
#define SH 8
#define SPIX (SH*WW)              // 6144
#define STRIPS_PER_IMG (HH/SH)    // 96
#define NSTRIP (BB*STRIPS_PER_IMG)// 768
#define NEDGE (BB*(STRIPS_PER_IMG-1)*WW)  // 583,680
#define SLOTS 1536                        // border slots per strip (2*WW)
#define NSLOT (NSTRIP*SLOTS)              // 1,179,648  (< 2^23)

// ---------------- static device scratch ----------------
__device__ __align__(16) unsigned char g_pm[NPIX]; // argmax class per pixel
__device__ int           g_uf[NSLOT];       // compact global UF over border slots (4.7MB)
__device__ int           g_btop[NSTRIP*WW]; // packed rep-slot of top-row pixels (-1 = bg)
__device__ int           g_bbot[NSTRIP*WW]; // packed rep-slot of bottom-row pixels
__device__ double        g_acc[4][20];      // [stat][cell]: 0=cnt 1=spho 2=slog 3=sl1p
__device__ int           g_lroots[4];       // Σ run-starts per class 1..4
__device__ int           g_merged[4];       // Σ successful UF links (in-strip + cross-strip)

// ---------------- K0: zero accumulators ----------------
__global__ void k_zero() {
    int t = threadIdx.x;
    if (t < 80) ((double*)g_acc)[t] = 0.0;
    if (t < 4) { g_lroots[t] = 0; g_merged[t] = 0; }
}

// ---------------- K1: argmax + joint stats (per-lane slabs, no atomics) ----------------
// grid (64, 8), block 128 -> 512 blocks total (single wave at 5 blocks/SM).
__global__ void __launch_bounds__(128) k_stats(const float* __restrict__ pred,
                                               const int*   __restrict__ tmask) {
    __shared__ float slab[4][4][20][32];   // [warp][stat][cell][lane] — bank-conflict free
    const int tid  = threadIdx.x;
    const int warp = tid >> 5, lane = tid & 31;
    for (int k = tid; k < 4*4*20*32; k += 128) ((float*)slab)[k] = 0.f;
    __syncthreads();

    const int img = blockIdx.y;
    const float* pb = pred + (size_t)img * CC * HW;
    const int4*  tb = (const int4*)(tmask + (size_t)img * HW);
    uchar4* pmb = (uchar4*)g_pm + (size_t)img * (HW/4);
    float* my = &slab[warp][0][0][lane];
    const int start = blockIdx.x * 2304;   // HW/4 / 64 = 2304 vec4 per block

    #pragma unroll 2
    for (int it = 0; it < 18; ++it) {
        int v = start + it * 128 + tid;       // vec4 index within image
        int j = v * 4;
        float4 c0 = *(const float4*)(pb + j);
        float4 c1 = *(const float4*)(pb + HW + j);
        float4 c2 = *(const float4*)(pb + 2*HW + j);
        float4 c3 = *(const float4*)(pb + 3*HW + j);
        float4 c4 = *(const float4*)(pb + 4*HW + j);
        int4  tv  = tb[v];

        float A0[4] = {c0.x, c0.y, c0.z, c0.w};
        float A1[4] = {c1.x, c1.y, c1.z, c1.w};
        float A2[4] = {c2.x, c2.y, c2.z, c2.w};
        float A3[4] = {c3.x, c3.y, c3.z, c3.w};
        float A4[4] = {c4.x, c4.y, c4.z, c4.w};
        int tvv[4] = {tv.x, tv.y, tv.z, tv.w};
        unsigned char bcs[4];

        #pragma unroll
        for (int e = 0; e < 4; e++) {
            float best = A0[e]; int bc = 0;
            if (A1[e] > best) { best = A1[e]; bc = 1; }
            if (A2[e] > best) { best = A2[e]; bc = 2; }
            if (A3[e] > best) { best = A3[e]; bc = 3; }
            if (A4[e] > best) { best = A4[e]; bc = 4; }
            bcs[e] = (unsigned char)bc;

            int t = tvv[e]; t = t < 0 ? 0 : (t > 3 ? 3 : t);
            int cell = t * 5 + bc;
            float q  = bc ? best : 0.0f;
            float qc = fminf(fmaxf(q, EPSF), ONEMF);
            float lg = __logf(qc);
            float l1 = __logf(1.0f - qc);
            float* p = my + cell * 32;        // stat stride = 20*32 = 640 floats
            p[0]    += 1.0f;
            p[640]  += q;
            p[1280] += lg;
            p[1920] += l1;
        }
        pmb[v] = make_uchar4(bcs[0], bcs[1], bcs[2], bcs[3]);
    }
    __syncthreads();

    if (tid < 80) {
        int s = tid / 20, c = tid % 20;
        double acc = 0.0;
        #pragma unroll
        for (int w = 0; w < 4; w++)
            for (int l = 0; l < 32; l++) acc += (double)slab[w][s][c][l];
        atomicAdd(&g_acc[s][c], acc);
    }
}

// ---------------- shared-memory union-find (monotone links) ----------------
__device__ __forceinline__ int find_s(int* lab, int x) {
    int r = x, l = lab[r];
    while (l != r) { r = l; l = lab[r]; }
    int c = x;
    while (c != r) { int n = lab[c]; if (n == r) break; lab[c] = r; c = n; }
    return r;
}
__device__ __forceinline__ bool union_s(int* lab, int a, int b) {
    while (true) {
        a = find_s(lab, a); b = find_s(lab, b);
        if (a == b) return false;
        if (a < b) { int t = a; a = b; b = t; }
        int old = atomicCAS(&lab[a], a, b);
        if (old == a) return true;     // exactly one root retired
        a = old;
    }
}

// ---------------- K2: per-strip CCL: chain-init + vertical unions + export ----------------
// smem ~33KB -> 6 blocks/SM, 768 blocks < 888 capacity -> single wave.
__global__ void __launch_bounds__(256) k_ccl() {
    __shared__ int lab[SPIX];                 // 24KB (repurposed as minpos in export)
    __shared__ unsigned char pm[SPIX];        // 6KB
    __shared__ unsigned short rootof[SLOTS];  // 3KB
    __shared__ int rc8[8];                    // [0..3]=runs, [4..7]=vsucc
    const int tid = threadIdx.x;
    const int lane = tid & 31;
    const int strip = blockIdx.x;
    const int base = strip * SPIX;

    for (int v = tid; v < SPIX/16; v += 256)
        ((int4*)pm)[v] = ((const int4*)(g_pm + base))[v];
    if (tid < 8) rc8[tid] = 0;
    __syncthreads();

    // Pass A: horizontal chains (free unions) + run-start counts. 6 uniform iters.
    int r1 = 0, r2 = 0, r3 = 0, r4 = 0;
    for (int v = tid; v < SPIX/4; v += 256) {
        int j = v * 4;
        uchar4 c = ((const uchar4*)pm)[v];
        unsigned char left0 = (v % (WW/4)) ? pm[j - 1] : (unsigned char)0xFF;
        int4 L;
        L.x = (c.x && left0 == c.x) ? j - 1 : j;
        L.y = (c.y && c.x  == c.y) ? j     : j + 1;
        L.z = (c.z && c.y  == c.z) ? j + 1 : j + 2;
        L.w = (c.w && c.z  == c.w) ? j + 2 : j + 3;
        ((int4*)lab)[v] = L;
        if (c.x && left0 != c.x) { r1 += (c.x==1); r2 += (c.x==2); r3 += (c.x==3); r4 += (c.x==4); }
        if (c.y && c.x  != c.y) { r1 += (c.y==1); r2 += (c.y==2); r3 += (c.y==3); r4 += (c.y==4); }
        if (c.z && c.y  != c.z) { r1 += (c.z==1); r2 += (c.z==2); r3 += (c.z==3); r4 += (c.z==4); }
        if (c.w && c.z  != c.w) { r1 += (c.w==1); r2 += (c.w==2); r3 += (c.w==3); r4 += (c.w==4); }
    }
    __syncthreads();

    // Pass B: vertical unions only (rows 1..7). 21 uniform iters.
    int v1 = 0, v2 = 0, v3 = 0, v4 = 0;
    for (int idx = tid; idx < SPIX - WW; idx += 256) {
        int j = idx + WW;
        int c = pm[j];
        if (c && pm[j - WW] == c) {
            if (union_s(lab, j, j - WW)) {
                v1 += (c==1); v2 += (c==2); v3 += (c==3); v4 += (c==4);
            }
        }
    }
    // block-reduce the 8 counters
    {
        int s;
        s = __reduce_add_sync(0xFFFFFFFFu, r1); if (lane==0 && s) atomicAdd(&rc8[0], s);
        s = __reduce_add_sync(0xFFFFFFFFu, r2); if (lane==0 && s) atomicAdd(&rc8[1], s);
        s = __reduce_add_sync(0xFFFFFFFFu, r3); if (lane==0 && s) atomicAdd(&rc8[2], s);
        s = __reduce_add_sync(0xFFFFFFFFu, r4); if (lane==0 && s) atomicAdd(&rc8[3], s);
        s = __reduce_add_sync(0xFFFFFFFFu, v1); if (lane==0 && s) atomicAdd(&rc8[4], s);
        s = __reduce_add_sync(0xFFFFFFFFu, v2); if (lane==0 && s) atomicAdd(&rc8[5], s);
        s = __reduce_add_sync(0xFFFFFFFFu, v3); if (lane==0 && s) atomicAdd(&rc8[6], s);
        s = __reduce_add_sync(0xFFFFFFFFu, v4); if (lane==0 && s) atomicAdd(&rc8[7], s);
    }
    __syncthreads();

    // Pass C: export borders. Resolve roots of border pixels first.
    for (int bp = tid; bp < SLOTS; bp += 256) {
        int j = (bp < WW) ? bp : (SPIX - WW) + (bp - WW);
        rootof[bp] = pm[j] ? (unsigned short)find_s(lab, j) : (unsigned short)0xFFFF;
    }
    __syncthreads();
    for (int v = tid; v < SPIX/4; v += 256)
        ((int4*)lab)[v] = make_int4(0x7FFFFFFF, 0x7FFFFFFF, 0x7FFFFFFF, 0x7FFFFFFF);
    __syncthreads();
    for (int bp = tid; bp < SLOTS; bp += 256) {
        unsigned short r = rootof[bp];
        if (r != 0xFFFF) atomicMin(&lab[r], bp);
    }
    __syncthreads();
    for (int bp = tid; bp < SLOTS; bp += 256) {
        int j = (bp < WW) ? bp : (SPIX - WW) + (bp - WW);
        int c = pm[j];
        int slot = strip * SLOTS + bp;
        int link = slot, val = -1;
        if (c) {
            int rep = lab[rootof[bp]];         // min border slot of this local root
            link = strip * SLOTS + rep;        // decreasing link (rep <= bp)
            val = link | (c << 23);
        }
        g_uf[slot] = link;                     // coalesced
        if (bp < WW) g_btop[strip * WW + bp] = val;
        else         g_bbot[strip * WW + (bp - WW)] = val;
    }
    if (tid < 4)      atomicAdd(&g_lroots[tid], rc8[tid]);
    else if (tid < 8) atomicAdd(&g_merged[tid - 4], rc8[tid]);
}

// ---------------- compact global union-find ----------------
__device__ __forceinline__ int uf_find_g(int x) {
    int r = x, l = g_uf[r];
    while (l != r) { r = l; l = g_uf[r]; }
    int c = x;
    while (c != r) { int n = g_uf[c]; if (n == r) break; g_uf[c] = r; c = n; }
    return r;
}
__device__ __forceinline__ bool uf_union_g(int a, int b) {
    while (true) {
        a = uf_find_g(a); b = uf_find_g(b);
        if (a == b) return false;
        if (a < b) { int t = a; a = b; b = t; }
        int old = atomicCAS(&g_uf[a], a, b);
        if (old == a) return true;
        a = old;
    }
}

// ---------------- K3: cross-strip border merge (deduped, compact table) ----------------
__global__ void __launch_bounds__(256) k_border() {
    int e = blockIdx.x * blockDim.x + threadIdx.x;
    int lane = threadIdx.x & 31;
    int myclass = 0;
    int va = -1, vb = -1;
    if (e < NEDGE) {
        int w  = e % WW;
        int bi = e / WW;
        int img = bi / (STRIPS_PER_IMG - 1);
        int brow = bi - img * (STRIPS_PER_IMG - 1);
        int s = img * STRIPS_PER_IMG + brow;
        va = g_bbot[s * WW + w];
        vb = g_btop[(s + 1) * WW + w];
    }
    int pva = __shfl_up_sync(0xFFFFFFFFu, va, 1);
    int pvb = __shfl_up_sync(0xFFFFFFFFu, vb, 1);
    bool dup = (lane > 0) && (va == pva) && (vb == pvb);
    if (e < NEDGE && !dup && (va | vb) >= 0) {
        int ca = va >> 23;
        if (ca == (vb >> 23)) {
            if (uf_union_g(va & 0x7FFFFF, vb & 0x7FFFFF)) myclass = ca;
        }
    }
    #pragma unroll
    for (int k = 1; k <= 4; k++) {
        unsigned m = __ballot_sync(0xFFFFFFFFu, myclass == k);
        if (lane == 0 && m) atomicAdd(&g_merged[k - 1], __popc(m));
    }
}

// ---------------- K4: scalar assembly ----------------
__global__ void k_final(float* __restrict__ out) {
    if (threadIdx.x != 0 || blockIdx.x != 0) return;

    long long cnt[4][5];
    double spho[4][5], slog[4][5], slog1p[4][5];
    for (int t = 0; t < 4; t++)
        for (int c = 0; c < 5; c++) {
            int k = t * 5 + c;
            cnt[t][c]    = (long long)(g_acc[0][k] + 0.5);
            spho[t][c]   = g_acc[1][k];
            slog[t][c]   = g_acc[2][k];
            slog1p[t][c] = g_acc[3][k];
        }
    long long cpm[5] = {0,0,0,0,0};
    long long ctm[4] = {0,0,0,0};
    for (int t = 0; t < 4; t++)
        for (int c = 0; c < 5; c++) { cpm[c] += cnt[t][c]; ctm[t] += cnt[t][c]; }

    // exact-f32 emulation of ph class values
    float phv[5] = {0.f,0.f,0.f,0.f,0.f};
    int last_i = 1;
    for (int v = 1; v < 5; v++) {
        bool present = (cpm[v] > 0);
        int has_bg = (cpm[v] < (long long)NPIX) ? 1 : 0;
        int nc = g_lroots[v - 1] - g_merged[v - 1];
        int wrapped = (int)((unsigned int)nc * (unsigned int)last_i);
        float s = (float)wrapped;
        if (present) {
            #pragma unroll
            for (int c = 0; c < 5; c++) {
                float ind = (c == v) ? 1.0f : 0.0f;
                float inc = ind + s;
                phv[c] = phv[c] + inc;
            }
            last_i += nc + has_bg;
        }
    }

    const double Nd = (double)NPIX;
    // Precomputed (double-exact) log constants for clip(0)=eps_f32 and clip(1)=1-2^-23
    const double LOG_EPS     = -16.1180956392722239;
    const double LOG_ONEM    = -1.1920929665620861e-07;
    const double LOG1P_NEPS  = -1.0000000616860977e-07;
    const double LOG1P_NONEM = -15.9423851528787421;

    double res = 0.0;

    { // term 0: bce_dice(pm==0, tm==0)
        long long n00 = cnt[0][0];
        long long np0 = cpm[0];
        long long nt0 = ctm[0];
        double bsum = (double)n00 * LOG_ONEM
                    + (double)(nt0 - n00) * LOG_EPS
                    + (double)(np0 - n00) * LOG1P_NONEM
                    + (double)((long long)NPIX - nt0 - np0 + n00) * LOG1P_NEPS;
        double bce = -bsum / Nd;
        double dice = 1.0 - (2.0 * (double)n00 + 1.0) / ((double)np0 + (double)nt0 + 1.0);
        res += bce + dice;
    }

    for (int t = 1; t < NTC; t++) {
        long long nt = ctm[t];
        if (nt <= 0) continue;

        int ord[5] = {0,1,2,3,4};
        for (int i = 1; i < 5; i++) {
            int o = ord[i]; float v = phv[o]; int j = i - 1;
            while (j >= 0 && phv[ord[j]] > v) { ord[j+1] = ord[j]; j--; }
            ord[j+1] = o;
        }
        long long kk = (nt - 1) / 2;
        float med = phv[ord[4]];
        long long cum = 0;
        for (int j = 0; j < 5; j++) {
            cum += cnt[t][ord[j]];
            if (cum > kk) { med = phv[ord[j]]; break; }
        }
        bool sel[5];
        #pragma unroll
        for (int c = 0; c < 5; c++) sel[c] = (phv[c] == med);

        double bsum = 0.0, sum_p = 0.0, inter = 0.0, extra_sum = 0.0;
        for (int c = 0; c < 5; c++) {
            if (sel[c]) {
                bsum += slog[t][c];
                inter += spho[t][c];
                for (int tt = 0; tt < 4; tt++) {
                    sum_p += spho[tt][c];
                    if (tt != t) bsum += slog1p[tt][c];
                }
            } else {
                bsum += (double)cnt[t][c] * LOG_EPS;
                extra_sum += spho[t][c];
                for (int tt = 0; tt < 4; tt++)
                    if (tt != t) bsum += (double)cnt[tt][c] * LOG1P_NEPS;
            }
        }
        double bce = -bsum / Nd;
        double dice = 1.0 - (2.0 * inter + 1.0) / (sum_p + (double)nt + 1.0);
        double extra = extra_sum / (double)(nt > 0 ? nt : 1);
        res += bce + dice + extra;
    }

    int nu = 0;
    for (int t = 0; t < NTC; t++) if (ctm[t] > 0) nu++;
    out[0] = (float)(res / (double)(2 * nu + 1));
}

// ---------------- launch ----------------
extern "C" void kernel_launch(void* const* d_in, const int* in_sizes, int n_in,
                              void* d_out, int out_size) {
    const float* pred = (const float*)d_in[0];
    const int*   tm   = (const int*)d_in[1];
    float* out = (float*)d_out;
    (void)in_sizes; (void)n_in; (void)out_size;

    k_zero<<<1, 96>>>();                       // slot 1
    k_stats<<<dim3(64, 8), 128>>>(pred, tm);   // slot 2 (512 blocks, single wave)
    k_ccl<<<NSTRIP, 256>>>();                  // slot 3 (768 blocks, single wave)
    k_border<<<(NEDGE + 255) / 256, 256>>>();  // slot 4 — profiled
    k_final<<<1, 1>>>(out);                    // slot 5
}

// round 6
// speedup vs baseline: 1.5393x; 1.2588x over previous
#include <cuda_runtime.h>
#include <math.h>
#include <stdint.h>

// Problem constants (fixed shapes from setup_inputs)
#define BB 8
#define CC 5
#define HH 768
#define WW 768
#define HW (HH*WW)
#define NPIX (BB*HW)          // 4,718,592
#define NTC 4

#define EPSF 1e-7f
#define ONEMF ((float)(1.0 - 1e-7))

// strips for local CCL
#define SH 8
#define SPIX (SH*WW)              // 6144
#define STRIPS_PER_IMG (HH/SH)    // 96
#define NSTRIP (BB*STRIPS_PER_IMG)// 768
#define NEDGE (BB*(STRIPS_PER_IMG-1)*WW)  // 583,680
#define SLOTS 1536                        // border slots per strip (2*WW)
#define NSLOT (NSTRIP*SLOTS)              // 1,179,648  (< 2^23)

// ---------------- static device scratch ----------------
__device__ __align__(16) unsigned char g_pm[NPIX]; // argmax class per pixel
__device__ int           g_uf[NSLOT];       // compact global UF over border slots (4.7MB)
__device__ int           g_btop[NSTRIP*WW]; // packed rep-slot of top-row pixels (-1 = bg)
__device__ int           g_bbot[NSTRIP*WW]; // packed rep-slot of bottom-row pixels
__device__ double        g_acc[4][20];      // [stat][cell]: 0=cnt 1=spho 2=slog 3=sl1p
__device__ int           g_lroots[4];       // Σ run-starts per class 1..4
__device__ int           g_merged[4];       // Σ successful UF links (in-strip + cross-strip)

// ---------------- K0: zero accumulators ----------------
__global__ void k_zero() {
    int t = threadIdx.x;
    if (t < 80) ((double*)g_acc)[t] = 0.0;
    if (t < 4) { g_lroots[t] = 0; g_merged[t] = 0; }
}

__global__ void k_nop() {}

// ---------------- K1: argmax + joint stats (per-lane slabs, no atomics) ----------------
// grid (64, 8), block 128 -> 512 blocks total (single wave at 5 blocks/SM).
__global__ void __launch_bounds__(128) k_stats(const float* __restrict__ pred,
                                               const int*   __restrict__ tmask) {
    __shared__ float slab[4][4][20][32];   // [warp][stat][cell][lane] — bank-conflict free
    const int tid  = threadIdx.x;
    const int warp = tid >> 5, lane = tid & 31;
    for (int k = tid; k < 4*4*20*32; k += 128) ((float*)slab)[k] = 0.f;
    __syncthreads();

    const int img = blockIdx.y;
    const float* pb = pred + (size_t)img * CC * HW;
    const int4*  tb = (const int4*)(tmask + (size_t)img * HW);
    uchar4* pmb = (uchar4*)g_pm + (size_t)img * (HW/4);
    float* my = &slab[warp][0][0][lane];
    const int start = blockIdx.x * 2304;   // HW/4 / 64 = 2304 vec4 per block

    #pragma unroll 2
    for (int it = 0; it < 18; ++it) {
        int v = start + it * 128 + tid;       // vec4 index within image
        int j = v * 4;
        float4 c0 = *(const float4*)(pb + j);
        float4 c1 = *(const float4*)(pb + HW + j);
        float4 c2 = *(const float4*)(pb + 2*HW + j);
        float4 c3 = *(const float4*)(pb + 3*HW + j);
        float4 c4 = *(const float4*)(pb + 4*HW + j);
        int4  tv  = tb[v];

        float A0[4] = {c0.x, c0.y, c0.z, c0.w};
        float A1[4] = {c1.x, c1.y, c1.z, c1.w};
        float A2[4] = {c2.x, c2.y, c2.z, c2.w};
        float A3[4] = {c3.x, c3.y, c3.z, c3.w};
        float A4[4] = {c4.x, c4.y, c4.z, c4.w};
        int tvv[4] = {tv.x, tv.y, tv.z, tv.w};
        unsigned char bcs[4];

        #pragma unroll
        for (int e = 0; e < 4; e++) {
            float best = A0[e]; int bc = 0;
            if (A1[e] > best) { best = A1[e]; bc = 1; }
            if (A2[e] > best) { best = A2[e]; bc = 2; }
            if (A3[e] > best) { best = A3[e]; bc = 3; }
            if (A4[e] > best) { best = A4[e]; bc = 4; }
            bcs[e] = (unsigned char)bc;

            int t = tvv[e]; t = t < 0 ? 0 : (t > 3 ? 3 : t);
            int cell = t * 5 + bc;
            float q  = bc ? best : 0.0f;
            float qc = fminf(fmaxf(q, EPSF), ONEMF);
            float lg = __logf(qc);
            float l1 = __logf(1.0f - qc);
            float* p = my + cell * 32;        // stat stride = 20*32 = 640 floats
            p[0]    += 1.0f;
            p[640]  += q;
            p[1280] += lg;
            p[1920] += l1;
        }
        pmb[v] = make_uchar4(bcs[0], bcs[1], bcs[2], bcs[3]);
    }
    __syncthreads();

    if (tid < 80) {
        int s = tid / 20, c = tid % 20;
        double acc = 0.0;
        #pragma unroll
        for (int w = 0; w < 4; w++)
            for (int l = 0; l < 32; l++) acc += (double)slab[w][s][c][l];
        atomicAdd(&g_acc[s][c], acc);
    }
}

// ---------------- shared-memory union-find (monotone links) ----------------
__device__ __forceinline__ int find_s(int* lab, int x) {
    int r = x, l = lab[r];
    while (l != r) { r = l; l = lab[r]; }
    int c = x;
    while (c != r) { int n = lab[c]; if (n == r) break; lab[c] = r; c = n; }
    return r;
}
__device__ __forceinline__ bool union_s(int* lab, int a, int b) {
    while (true) {
        a = find_s(lab, a); b = find_s(lab, b);
        if (a == b) return false;
        if (a < b) { int t = a; a = b; b = t; }
        int old = atomicCAS(&lab[a], a, b);
        if (old == a) return true;     // exactly one root retired
        a = old;
    }
}

// ---------------- K2: per-strip CCL: chain-init + vertical unions + export ----------------
__global__ void __launch_bounds__(256) k_ccl() {
    __shared__ int lab[SPIX];                 // 24KB (repurposed as minpos in export)
    __shared__ unsigned char pm[SPIX];        // 6KB
    __shared__ unsigned short rootof[SLOTS];  // 3KB
    __shared__ int rc8[8];                    // [0..3]=runs, [4..7]=vsucc
    const int tid = threadIdx.x;
    const int lane = tid & 31;
    const int strip = blockIdx.x;
    const int base = strip * SPIX;

    for (int v = tid; v < SPIX/16; v += 256)
        ((int4*)pm)[v] = ((const int4*)(g_pm + base))[v];
    if (tid < 8) rc8[tid] = 0;
    __syncthreads();

    // Pass A: horizontal chains (free unions) + run-start counts.
    int r1 = 0, r2 = 0, r3 = 0, r4 = 0;
    for (int v = tid; v < SPIX/4; v += 256) {
        int j = v * 4;
        uchar4 c = ((const uchar4*)pm)[v];
        unsigned char left0 = (v % (WW/4)) ? pm[j - 1] : (unsigned char)0xFF;
        int4 L;
        L.x = (c.x && left0 == c.x) ? j - 1 : j;
        L.y = (c.y && c.x  == c.y) ? j     : j + 1;
        L.z = (c.z && c.y  == c.z) ? j + 1 : j + 2;
        L.w = (c.w && c.z  == c.w) ? j + 2 : j + 3;
        ((int4*)lab)[v] = L;
        if (c.x && left0 != c.x) { r1 += (c.x==1); r2 += (c.x==2); r3 += (c.x==3); r4 += (c.x==4); }
        if (c.y && c.x  != c.y) { r1 += (c.y==1); r2 += (c.y==2); r3 += (c.y==3); r4 += (c.y==4); }
        if (c.z && c.y  != c.z) { r1 += (c.z==1); r2 += (c.z==2); r3 += (c.z==3); r4 += (c.z==4); }
        if (c.w && c.z  != c.w) { r1 += (c.w==1); r2 += (c.w==2); r3 += (c.w==3); r4 += (c.w==4); }
    }
    __syncthreads();

    // Pass B: vertical unions only (rows 1..7).
    int v1 = 0, v2 = 0, v3 = 0, v4 = 0;
    for (int idx = tid; idx < SPIX - WW; idx += 256) {
        int j = idx + WW;
        int c = pm[j];
        if (c && pm[j - WW] == c) {
            if (union_s(lab, j, j - WW)) {
                v1 += (c==1); v2 += (c==2); v3 += (c==3); v4 += (c==4);
            }
        }
    }
    {
        int s;
        s = __reduce_add_sync(0xFFFFFFFFu, r1); if (lane==0 && s) atomicAdd(&rc8[0], s);
        s = __reduce_add_sync(0xFFFFFFFFu, r2); if (lane==0 && s) atomicAdd(&rc8[1], s);
        s = __reduce_add_sync(0xFFFFFFFFu, r3); if (lane==0 && s) atomicAdd(&rc8[2], s);
        s = __reduce_add_sync(0xFFFFFFFFu, r4); if (lane==0 && s) atomicAdd(&rc8[3], s);
        s = __reduce_add_sync(0xFFFFFFFFu, v1); if (lane==0 && s) atomicAdd(&rc8[4], s);
        s = __reduce_add_sync(0xFFFFFFFFu, v2); if (lane==0 && s) atomicAdd(&rc8[5], s);
        s = __reduce_add_sync(0xFFFFFFFFu, v3); if (lane==0 && s) atomicAdd(&rc8[6], s);
        s = __reduce_add_sync(0xFFFFFFFFu, v4); if (lane==0 && s) atomicAdd(&rc8[7], s);
    }
    __syncthreads();

    // Pass C: export borders.
    for (int bp = tid; bp < SLOTS; bp += 256) {
        int j = (bp < WW) ? bp : (SPIX - WW) + (bp - WW);
        rootof[bp] = pm[j] ? (unsigned short)find_s(lab, j) : (unsigned short)0xFFFF;
    }
    __syncthreads();
    for (int v = tid; v < SPIX/4; v += 256)
        ((int4*)lab)[v] = make_int4(0x7FFFFFFF, 0x7FFFFFFF, 0x7FFFFFFF, 0x7FFFFFFF);
    __syncthreads();
    for (int bp = tid; bp < SLOTS; bp += 256) {
        unsigned short r = rootof[bp];
        if (r != 0xFFFF) atomicMin(&lab[r], bp);
    }
    __syncthreads();
    for (int bp = tid; bp < SLOTS; bp += 256) {
        int j = (bp < WW) ? bp : (SPIX - WW) + (bp - WW);
        int c = pm[j];
        int slot = strip * SLOTS + bp;
        int link = slot, val = -1;
        if (c) {
            int rep = lab[rootof[bp]];         // min border slot of this local root
            link = strip * SLOTS + rep;        // decreasing link (rep <= bp)
            val = link | (c << 23);
        }
        g_uf[slot] = link;                     // coalesced
        if (bp < WW) g_btop[strip * WW + bp] = val;
        else         g_bbot[strip * WW + (bp - WW)] = val;
    }
    if (tid < 4)      atomicAdd(&g_lroots[tid], rc8[tid]);
    else if (tid < 8) atomicAdd(&g_merged[tid - 4], rc8[tid]);
}

// ---------------- compact global union-find ----------------
__device__ __forceinline__ int uf_find_g(int x) {
    int r = x, l = g_uf[r];
    while (l != r) { r = l; l = g_uf[r]; }
    int c = x;
    while (c != r) { int n = g_uf[c]; if (n == r) break; g_uf[c] = r; c = n; }
    return r;
}
__device__ __forceinline__ bool uf_union_g(int a, int b) {
    while (true) {
        a = uf_find_g(a); b = uf_find_g(b);
        if (a == b) return false;
        if (a < b) { int t = a; a = b; b = t; }
        int old = atomicCAS(&g_uf[a], a, b);
        if (old == a) return true;
        a = old;
    }
}

// ---------------- K3: cross-strip border merge (block-aggregated counters) ----------------
__global__ void __launch_bounds__(512) k_border() {
    __shared__ int s_m[4];
    if (threadIdx.x < 4) s_m[threadIdx.x] = 0;
    __syncthreads();

    int e = blockIdx.x * blockDim.x + threadIdx.x;
    int lane = threadIdx.x & 31;
    int myclass = 0;
    int va = -1, vb = -1;
    if (e < NEDGE) {
        int w  = e % WW;
        int bi = e / WW;
        int img = bi / (STRIPS_PER_IMG - 1);
        int brow = bi - img * (STRIPS_PER_IMG - 1);
        int s = img * STRIPS_PER_IMG + brow;
        va = g_bbot[s * WW + w];
        vb = g_btop[(s + 1) * WW + w];
    }
    int pva = __shfl_up_sync(0xFFFFFFFFu, va, 1);
    int pvb = __shfl_up_sync(0xFFFFFFFFu, vb, 1);
    bool dup = (lane > 0) && (va == pva) && (vb == pvb);
    if (e < NEDGE && !dup && (va | vb) >= 0) {
        int ca = va >> 23;
        if (ca == (vb >> 23)) {
            if (uf_union_g(va & 0x7FFFFF, vb & 0x7FFFFF)) myclass = ca;
        }
    }
    if (myclass) atomicAdd(&s_m[myclass - 1], 1);   // shared: cheap, sparse
    __syncthreads();
    if (threadIdx.x < 4 && s_m[threadIdx.x])
        atomicAdd(&g_merged[threadIdx.x], s_m[threadIdx.x]);  // 4 per block
}

// ---------------- K4: scalar assembly ----------------
__global__ void k_final(float* __restrict__ out) {
    if (threadIdx.x != 0 || blockIdx.x != 0) return;

    long long cnt[4][5];
    double spho[4][5], slog[4][5], slog1p[4][5];
    for (int t = 0; t < 4; t++)
        for (int c = 0; c < 5; c++) {
            int k = t * 5 + c;
            cnt[t][c]    = (long long)(g_acc[0][k] + 0.5);
            spho[t][c]   = g_acc[1][k];
            slog[t][c]   = g_acc[2][k];
            slog1p[t][c] = g_acc[3][k];
        }
    long long cpm[5] = {0,0,0,0,0};
    long long ctm[4] = {0,0,0,0};
    for (int t = 0; t < 4; t++)
        for (int c = 0; c < 5; c++) { cpm[c] += cnt[t][c]; ctm[t] += cnt[t][c]; }

    // exact-f32 emulation of ph class values
    float phv[5] = {0.f,0.f,0.f,0.f,0.f};
    int last_i = 1;
    for (int v = 1; v < 5; v++) {
        bool present = (cpm[v] > 0);
        int has_bg = (cpm[v] < (long long)NPIX) ? 1 : 0;
        int nc = g_lroots[v - 1] - g_merged[v - 1];
        int wrapped = (int)((unsigned int)nc * (unsigned int)last_i);
        float s = (float)wrapped;
        if (present) {
            #pragma unroll
            for (int c = 0; c < 5; c++) {
                float ind = (c == v) ? 1.0f : 0.0f;
                float inc = ind + s;
                phv[c] = phv[c] + inc;
            }
            last_i += nc + has_bg;
        }
    }

    const double Nd = (double)NPIX;
    // Precomputed (double-exact) log constants for clip(0)=eps_f32 and clip(1)=1-2^-23
    const double LOG_EPS     = -16.1180956392722239;
    const double LOG_ONEM    = -1.1920929665620861e-07;
    const double LOG1P_NEPS  = -1.0000000616860977e-07;
    const double LOG1P_NONEM = -15.9423851528787421;

    double res = 0.0;

    { // term 0: bce_dice(pm==0, tm==0)
        long long n00 = cnt[0][0];
        long long np0 = cpm[0];
        long long nt0 = ctm[0];
        double bsum = (double)n00 * LOG_ONEM
                    + (double)(nt0 - n00) * LOG_EPS
                    + (double)(np0 - n00) * LOG1P_NONEM
                    + (double)((long long)NPIX - nt0 - np0 + n00) * LOG1P_NEPS;
        double bce = -bsum / Nd;
        double dice = 1.0 - (2.0 * (double)n00 + 1.0) / ((double)np0 + (double)nt0 + 1.0);
        res += bce + dice;
    }

    for (int t = 1; t < NTC; t++) {
        long long nt = ctm[t];
        if (nt <= 0) continue;

        int ord[5] = {0,1,2,3,4};
        for (int i = 1; i < 5; i++) {
            int o = ord[i]; float v = phv[o]; int j = i - 1;
            while (j >= 0 && phv[ord[j]] > v) { ord[j+1] = ord[j]; j--; }
            ord[j+1] = o;
        }
        long long kk = (nt - 1) / 2;
        float med = phv[ord[4]];
        long long cum = 0;
        for (int j = 0; j < 5; j++) {
            cum += cnt[t][ord[j]];
            if (cum > kk) { med = phv[ord[j]]; break; }
        }
        bool sel[5];
        #pragma unroll
        for (int c = 0; c < 5; c++) sel[c] = (phv[c] == med);

        double bsum = 0.0, sum_p = 0.0, inter = 0.0, extra_sum = 0.0;
        for (int c = 0; c < 5; c++) {
            if (sel[c]) {
                bsum += slog[t][c];
                inter += spho[t][c];
                for (int tt = 0; tt < 4; tt++) {
                    sum_p += spho[tt][c];
                    if (tt != t) bsum += slog1p[tt][c];
                }
            } else {
                bsum += (double)cnt[t][c] * LOG_EPS;
                extra_sum += spho[t][c];
                for (int tt = 0; tt < 4; tt++)
                    if (tt != t) bsum += (double)cnt[tt][c] * LOG1P_NEPS;
            }
        }
        double bce = -bsum / Nd;
        double dice = 1.0 - (2.0 * inter + 1.0) / (sum_p + (double)nt + 1.0);
        double extra = extra_sum / (double)(nt > 0 ? nt : 1);
        res += bce + dice + extra;
    }

    int nu = 0;
    for (int t = 0; t < NTC; t++) if (ctm[t] > 0) nu++;
    out[0] = (float)(res / (double)(2 * nu + 1));
}

// ---------------- launch ----------------
extern "C" void kernel_launch(void* const* d_in, const int* in_sizes, int n_in,
                              void* d_out, int out_size) {
    const float* pred = (const float*)d_in[0];
    const int*   tm   = (const int*)d_in[1];
    float* out = (float*)d_out;
    (void)in_sizes; (void)n_in; (void)out_size;

    k_zero<<<1, 96>>>();                       // slot 1
    k_nop<<<1, 32>>>();                        // slot 2
    k_nop<<<1, 32>>>();                        // slot 3
    k_stats<<<dim3(64, 8), 128>>>(pred, tm);   // slot 4 — profiled this round
    k_ccl<<<NSTRIP, 256>>>();                  // slot 5
    k_border<<<(NEDGE + 511) / 512, 512>>>();  // slot 6
    k_final<<<1, 1>>>(out);                    // slot 7
}

// round 7
// speedup vs baseline: 1.7137x; 1.1133x over previous
#include <cuda_runtime.h>
#include <math.h>
#include <stdint.h>

// Problem constants (fixed shapes from setup_inputs)
#define BB 8
#define CC 5
#define HH 768
#define WW 768
#define HW (HH*WW)
#define NPIX (BB*HW)          // 4,718,592
#define NV4  (NPIX/4)         // 1,179,648
#define HWV4 (HW/4)           // 147,456
#define NTC 4

#define EPSF 1e-7f
#define ONEMF ((float)(1.0 - 1e-7))

// strips for local CCL
#define SH 8
#define SPIX (SH*WW)              // 6144
#define STRIPS_PER_IMG (HH/SH)    // 96
#define NSTRIP (BB*STRIPS_PER_IMG)// 768
#define NEDGE (BB*(STRIPS_PER_IMG-1)*WW)  // 583,680
#define SLOTS 1536                        // border slots per strip (2*WW)
#define NSLOT (NSTRIP*SLOTS)              // 1,179,648  (< 2^23)

// ---------------- static device scratch ----------------
__device__ __align__(16) unsigned char g_pm[NPIX]; // argmax class per pixel
__device__ int           g_uf[NSLOT];       // compact global UF over border slots (4.7MB)
__device__ int           g_btop[NSTRIP*WW]; // packed rep-slot of top-row pixels (-1 = bg)
__device__ int           g_bbot[NSTRIP*WW]; // packed rep-slot of bottom-row pixels
__device__ double        g_acc[4][20];      // [stat][cell]: 1=spho 2=slog 3=sl1p (0 unused)
__device__ int           g_cnt[20];         // exact joint counts [tm][pm]
__device__ int           g_lroots[4];       // Σ run-starts per class 1..4
__device__ int           g_merged[4];       // Σ successful UF links (in-strip + cross-strip)

// ---------------- K0: zero accumulators ----------------
__global__ void k_zero() {
    int t = threadIdx.x;
    if (t < 80) ((double*)g_acc)[t] = 0.0;
    if (t < 20) g_cnt[t] = 0;
    if (t < 4) { g_lroots[t] = 0; g_merged[t] = 0; }
}

__global__ void k_nop() {}

// ---------------- K1: argmax + joint stats ----------------
// 888 blocks = 6/SM x 148 SMs (exact capacity, single wave). Slab 30KB (3 float stats);
// counts live in packed per-thread registers (1 byte per cell, <=44 pixels/thread).
__global__ void __launch_bounds__(128, 6) k_stats(const float* __restrict__ pred,
                                                  const int*   __restrict__ tmask) {
    __shared__ float slab[4][3][20][32];   // [warp][stat][cell][lane] — bank-conflict free
    __shared__ int s_cnt[20];
    const int tid  = threadIdx.x;
    const int warp = tid >> 5, lane = tid & 31;
    for (int k = tid; k < 4*3*20*32; k += 128) ((float*)slab)[k] = 0.f;
    if (tid < 20) s_cnt[tid] = 0;
    __syncthreads();

    float* my = &slab[warp][0][0][lane];
    unsigned int pc[5] = {0u, 0u, 0u, 0u, 0u};   // packed byte counters for 20 cells

    const int stride = gridDim.x * 128;
    for (int v = blockIdx.x * 128 + tid; v < NV4; v += stride) {
        int img = v / HWV4;                 // constant division -> mul
        int vin = v - img * HWV4;
        const float* pb = pred + (size_t)img * CC * HW;
        int j = vin * 4;
        float4 c0 = *(const float4*)(pb + j);
        float4 c1 = *(const float4*)(pb + HW + j);
        float4 c2 = *(const float4*)(pb + 2*HW + j);
        float4 c3 = *(const float4*)(pb + 3*HW + j);
        float4 c4 = *(const float4*)(pb + 4*HW + j);
        int4  tv  = ((const int4*)tmask)[v];

        float A0[4] = {c0.x, c0.y, c0.z, c0.w};
        float A1[4] = {c1.x, c1.y, c1.z, c1.w};
        float A2[4] = {c2.x, c2.y, c2.z, c2.w};
        float A3[4] = {c3.x, c3.y, c3.z, c3.w};
        float A4[4] = {c4.x, c4.y, c4.z, c4.w};
        int tvv[4] = {tv.x, tv.y, tv.z, tv.w};
        unsigned char bcs[4];

        #pragma unroll
        for (int e = 0; e < 4; e++) {
            float best = A0[e]; int bc = 0;
            if (A1[e] > best) { best = A1[e]; bc = 1; }
            if (A2[e] > best) { best = A2[e]; bc = 2; }
            if (A3[e] > best) { best = A3[e]; bc = 3; }
            if (A4[e] > best) { best = A4[e]; bc = 4; }
            bcs[e] = (unsigned char)bc;

            int t = tvv[e]; t = t < 0 ? 0 : (t > 3 ? 3 : t);
            int cell = t * 5 + bc;
            pc[cell >> 2] += 1u << ((cell & 3) * 8);

            float q  = bc ? best : 0.0f;
            float qc = fminf(fmaxf(q, EPSF), ONEMF);
            float lg = __logf(qc);
            float l1 = __logf(1.0f - qc);
            float* p = my + cell * 32;        // stat stride = 20*32 = 640 floats
            p[0]    += q;
            p[640]  += lg;
            p[1280] += l1;
        }
        ((uchar4*)g_pm)[v] = make_uchar4(bcs[0], bcs[1], bcs[2], bcs[3]);
    }

    // counts: warp-reduce packed bytes (two 16-bit halves), then shared, then global
    #pragma unroll
    for (int k = 0; k < 5; k++) {
        unsigned x = pc[k];
        unsigned lo = __reduce_add_sync(0xFFFFFFFFu, x & 0x00FF00FFu);
        unsigned hi = __reduce_add_sync(0xFFFFFFFFu, (x >> 8) & 0x00FF00FFu);
        if (lane == 0) {
            if (lo & 0xFFFFu) atomicAdd(&s_cnt[k*4 + 0], (int)(lo & 0xFFFFu));
            if (lo >> 16)     atomicAdd(&s_cnt[k*4 + 2], (int)(lo >> 16));
            if (hi & 0xFFFFu) atomicAdd(&s_cnt[k*4 + 1], (int)(hi & 0xFFFFu));
            if (hi >> 16)     atomicAdd(&s_cnt[k*4 + 3], (int)(hi >> 16));
        }
    }
    __syncthreads();

    if (tid < 60) {
        int s = tid / 20, c = tid % 20;
        double acc = 0.0;
        #pragma unroll
        for (int w = 0; w < 4; w++)
            for (int l = 0; l < 32; l++) acc += (double)slab[w][s][c][l];
        atomicAdd(&g_acc[s + 1][c], acc);
    }
    if (tid < 20 && s_cnt[tid]) atomicAdd(&g_cnt[tid], s_cnt[tid]);
}

// ---------------- shared-memory union-find (monotone links) ----------------
__device__ __forceinline__ int find_s(int* lab, int x) {
    int r = x, l = lab[r];
    while (l != r) { r = l; l = lab[r]; }
    int c = x;
    while (c != r) { int n = lab[c]; if (n == r) break; lab[c] = r; c = n; }
    return r;
}
__device__ __forceinline__ bool union_s(int* lab, int a, int b) {
    while (true) {
        a = find_s(lab, a); b = find_s(lab, b);
        if (a == b) return false;
        if (a < b) { int t = a; a = b; b = t; }
        int old = atomicCAS(&lab[a], a, b);
        if (old == a) return true;     // exactly one root retired
        a = old;
    }
}

// ---------------- K2: per-strip CCL: chain-init + vertical unions + export ----------------
__global__ void __launch_bounds__(256) k_ccl() {
    __shared__ int lab[SPIX];                 // 24KB (repurposed as minpos in export)
    __shared__ unsigned char pm[SPIX];        // 6KB
    __shared__ unsigned short rootof[SLOTS];  // 3KB
    __shared__ int rc8[8];                    // [0..3]=runs, [4..7]=vsucc
    const int tid = threadIdx.x;
    const int lane = tid & 31;
    const int strip = blockIdx.x;
    const int base = strip * SPIX;

    for (int v = tid; v < SPIX/16; v += 256)
        ((int4*)pm)[v] = ((const int4*)(g_pm + base))[v];
    if (tid < 8) rc8[tid] = 0;
    __syncthreads();

    // Pass A: horizontal chains (free unions) + run-start counts.
    int r1 = 0, r2 = 0, r3 = 0, r4 = 0;
    for (int v = tid; v < SPIX/4; v += 256) {
        int j = v * 4;
        uchar4 c = ((const uchar4*)pm)[v];
        unsigned char left0 = (v % (WW/4)) ? pm[j - 1] : (unsigned char)0xFF;
        int4 L;
        L.x = (c.x && left0 == c.x) ? j - 1 : j;
        L.y = (c.y && c.x  == c.y) ? j     : j + 1;
        L.z = (c.z && c.y  == c.z) ? j + 1 : j + 2;
        L.w = (c.w && c.z  == c.w) ? j + 2 : j + 3;
        ((int4*)lab)[v] = L;
        if (c.x && left0 != c.x) { r1 += (c.x==1); r2 += (c.x==2); r3 += (c.x==3); r4 += (c.x==4); }
        if (c.y && c.x  != c.y) { r1 += (c.y==1); r2 += (c.y==2); r3 += (c.y==3); r4 += (c.y==4); }
        if (c.z && c.y  != c.z) { r1 += (c.z==1); r2 += (c.z==2); r3 += (c.z==3); r4 += (c.z==4); }
        if (c.w && c.z  != c.w) { r1 += (c.w==1); r2 += (c.w==2); r3 += (c.w==3); r4 += (c.w==4); }
    }
    __syncthreads();

    // Pass B: vertical unions only (rows 1..7).
    int v1 = 0, v2 = 0, v3 = 0, v4 = 0;
    for (int idx = tid; idx < SPIX - WW; idx += 256) {
        int j = idx + WW;
        int c = pm[j];
        if (c && pm[j - WW] == c) {
            if (union_s(lab, j, j - WW)) {
                v1 += (c==1); v2 += (c==2); v3 += (c==3); v4 += (c==4);
            }
        }
    }
    {
        int s;
        s = __reduce_add_sync(0xFFFFFFFFu, r1); if (lane==0 && s) atomicAdd(&rc8[0], s);
        s = __reduce_add_sync(0xFFFFFFFFu, r2); if (lane==0 && s) atomicAdd(&rc8[1], s);
        s = __reduce_add_sync(0xFFFFFFFFu, r3); if (lane==0 && s) atomicAdd(&rc8[2], s);
        s = __reduce_add_sync(0xFFFFFFFFu, r4); if (lane==0 && s) atomicAdd(&rc8[3], s);
        s = __reduce_add_sync(0xFFFFFFFFu, v1); if (lane==0 && s) atomicAdd(&rc8[4], s);
        s = __reduce_add_sync(0xFFFFFFFFu, v2); if (lane==0 && s) atomicAdd(&rc8[5], s);
        s = __reduce_add_sync(0xFFFFFFFFu, v3); if (lane==0 && s) atomicAdd(&rc8[6], s);
        s = __reduce_add_sync(0xFFFFFFFFu, v4); if (lane==0 && s) atomicAdd(&rc8[7], s);
    }
    __syncthreads();

    // Pass C: export borders.
    for (int bp = tid; bp < SLOTS; bp += 256) {
        int j = (bp < WW) ? bp : (SPIX - WW) + (bp - WW);
        rootof[bp] = pm[j] ? (unsigned short)find_s(lab, j) : (unsigned short)0xFFFF;
    }
    __syncthreads();
    for (int v = tid; v < SPIX/4; v += 256)
        ((int4*)lab)[v] = make_int4(0x7FFFFFFF, 0x7FFFFFFF, 0x7FFFFFFF, 0x7FFFFFFF);
    __syncthreads();
    for (int bp = tid; bp < SLOTS; bp += 256) {
        unsigned short r = rootof[bp];
        if (r != 0xFFFF) atomicMin(&lab[r], bp);
    }
    __syncthreads();
    for (int bp = tid; bp < SLOTS; bp += 256) {
        int j = (bp < WW) ? bp : (SPIX - WW) + (bp - WW);
        int c = pm[j];
        int slot = strip * SLOTS + bp;
        int link = slot, val = -1;
        if (c) {
            int rep = lab[rootof[bp]];         // min border slot of this local root
            link = strip * SLOTS + rep;        // decreasing link (rep <= bp)
            val = link | (c << 23);
        }
        g_uf[slot] = link;                     // coalesced
        if (bp < WW) g_btop[strip * WW + bp] = val;
        else         g_bbot[strip * WW + (bp - WW)] = val;
    }
    if (tid < 4)      atomicAdd(&g_lroots[tid], rc8[tid]);
    else if (tid < 8) atomicAdd(&g_merged[tid - 4], rc8[tid]);
}

// ---------------- compact global union-find ----------------
__device__ __forceinline__ int uf_find_g(int x) {
    int r = x, l = g_uf[r];
    while (l != r) { r = l; l = g_uf[r]; }
    int c = x;
    while (c != r) { int n = g_uf[c]; if (n == r) break; g_uf[c] = r; c = n; }
    return r;
}
__device__ __forceinline__ bool uf_union_g(int a, int b) {
    while (true) {
        a = uf_find_g(a); b = uf_find_g(b);
        if (a == b) return false;
        if (a < b) { int t = a; a = b; b = t; }
        int old = atomicCAS(&g_uf[a], a, b);
        if (old == a) return true;
        a = old;
    }
}

// ---------------- K3: cross-strip border merge (block-aggregated counters) ----------------
__global__ void __launch_bounds__(512) k_border() {
    __shared__ int s_m[4];
    if (threadIdx.x < 4) s_m[threadIdx.x] = 0;
    __syncthreads();

    int e = blockIdx.x * blockDim.x + threadIdx.x;
    int lane = threadIdx.x & 31;
    int myclass = 0;
    int va = -1, vb = -1;
    if (e < NEDGE) {
        int w  = e % WW;
        int bi = e / WW;
        int img = bi / (STRIPS_PER_IMG - 1);
        int brow = bi - img * (STRIPS_PER_IMG - 1);
        int s = img * STRIPS_PER_IMG + brow;
        va = g_bbot[s * WW + w];
        vb = g_btop[(s + 1) * WW + w];
    }
    int pva = __shfl_up_sync(0xFFFFFFFFu, va, 1);
    int pvb = __shfl_up_sync(0xFFFFFFFFu, vb, 1);
    bool dup = (lane > 0) && (va == pva) && (vb == pvb);
    if (e < NEDGE && !dup && (va | vb) >= 0) {
        int ca = va >> 23;
        if (ca == (vb >> 23)) {
            if (uf_union_g(va & 0x7FFFFF, vb & 0x7FFFFF)) myclass = ca;
        }
    }
    if (myclass) atomicAdd(&s_m[myclass - 1], 1);
    __syncthreads();
    if (threadIdx.x < 4 && s_m[threadIdx.x])
        atomicAdd(&g_merged[threadIdx.x], s_m[threadIdx.x]);
}

// ---------------- K4: scalar assembly ----------------
__global__ void k_final(float* __restrict__ out) {
    if (threadIdx.x != 0 || blockIdx.x != 0) return;

    long long cnt[4][5];
    double spho[4][5], slog[4][5], slog1p[4][5];
    for (int t = 0; t < 4; t++)
        for (int c = 0; c < 5; c++) {
            int k = t * 5 + c;
            cnt[t][c]    = (long long)g_cnt[k];
            spho[t][c]   = g_acc[1][k];
            slog[t][c]   = g_acc[2][k];
            slog1p[t][c] = g_acc[3][k];
        }
    long long cpm[5] = {0,0,0,0,0};
    long long ctm[4] = {0,0,0,0};
    for (int t = 0; t < 4; t++)
        for (int c = 0; c < 5; c++) { cpm[c] += cnt[t][c]; ctm[t] += cnt[t][c]; }

    // exact-f32 emulation of ph class values
    float phv[5] = {0.f,0.f,0.f,0.f,0.f};
    int last_i = 1;
    for (int v = 1; v < 5; v++) {
        bool present = (cpm[v] > 0);
        int has_bg = (cpm[v] < (long long)NPIX) ? 1 : 0;
        int nc = g_lroots[v - 1] - g_merged[v - 1];
        int wrapped = (int)((unsigned int)nc * (unsigned int)last_i);
        float s = (float)wrapped;
        if (present) {
            #pragma unroll
            for (int c = 0; c < 5; c++) {
                float ind = (c == v) ? 1.0f : 0.0f;
                float inc = ind + s;
                phv[c] = phv[c] + inc;
            }
            last_i += nc + has_bg;
        }
    }

    const double Nd = (double)NPIX;
    // Precomputed (double-exact) log constants for clip(0)=eps_f32 and clip(1)=1-2^-23
    const double LOG_EPS     = -16.1180956392722239;
    const double LOG_ONEM    = -1.1920929665620861e-07;
    const double LOG1P_NEPS  = -1.0000000616860977e-07;
    const double LOG1P_NONEM = -15.9423851528787421;

    double res = 0.0;

    { // term 0: bce_dice(pm==0, tm==0)
        long long n00 = cnt[0][0];
        long long np0 = cpm[0];
        long long nt0 = ctm[0];
        double bsum = (double)n00 * LOG_ONEM
                    + (double)(nt0 - n00) * LOG_EPS
                    + (double)(np0 - n00) * LOG1P_NONEM
                    + (double)((long long)NPIX - nt0 - np0 + n00) * LOG1P_NEPS;
        double bce = -bsum / Nd;
        double dice = 1.0 - (2.0 * (double)n00 + 1.0) / ((double)np0 + (double)nt0 + 1.0);
        res += bce + dice;
    }

    for (int t = 1; t < NTC; t++) {
        long long nt = ctm[t];
        if (nt <= 0) continue;

        int ord[5] = {0,1,2,3,4};
        for (int i = 1; i < 5; i++) {
            int o = ord[i]; float v = phv[o]; int j = i - 1;
            while (j >= 0 && phv[ord[j]] > v) { ord[j+1] = ord[j]; j--; }
            ord[j+1] = o;
        }
        long long kk = (nt - 1) / 2;
        float med = phv[ord[4]];
        long long cum = 0;
        for (int j = 0; j < 5; j++) {
            cum += cnt[t][ord[j]];
            if (cum > kk) { med = phv[ord[j]]; break; }
        }
        bool sel[5];
        #pragma unroll
        for (int c = 0; c < 5; c++) sel[c] = (phv[c] == med);

        double bsum = 0.0, sum_p = 0.0, inter = 0.0, extra_sum = 0.0;
        for (int c = 0; c < 5; c++) {
            if (sel[c]) {
                bsum += slog[t][c];
                inter += spho[t][c];
                for (int tt = 0; tt < 4; tt++) {
                    sum_p += spho[tt][c];
                    if (tt != t) bsum += slog1p[tt][c];
                }
            } else {
                bsum += (double)cnt[t][c] * LOG_EPS;
                extra_sum += spho[t][c];
                for (int tt = 0; tt < 4; tt++)
                    if (tt != t) bsum += (double)cnt[tt][c] * LOG1P_NEPS;
            }
        }
        double bce = -bsum / Nd;
        double dice = 1.0 - (2.0 * inter + 1.0) / (sum_p + (double)nt + 1.0);
        double extra = extra_sum / (double)(nt > 0 ? nt : 1);
        res += bce + dice + extra;
    }

    int nu = 0;
    for (int t = 0; t < NTC; t++) if (ctm[t] > 0) nu++;
    out[0] = (float)(res / (double)(2 * nu + 1));
}

// ---------------- launch ----------------
extern "C" void kernel_launch(void* const* d_in, const int* in_sizes, int n_in,
                              void* d_out, int out_size) {
    const float* pred = (const float*)d_in[0];
    const int*   tm   = (const int*)d_in[1];
    float* out = (float*)d_out;
    (void)in_sizes; (void)n_in; (void)out_size;

    k_zero<<<1, 96>>>();                       // slot 1
    k_stats<<<888, 128>>>(pred, tm);           // slot 2 (6 blocks/SM x 148, single wave)
    k_nop<<<1, 32>>>();                        // slot 3
    k_ccl<<<NSTRIP, 256>>>();                  // slot 4 — profiled this round
    k_border<<<(NEDGE + 511) / 512, 512>>>();  // slot 5
    k_final<<<1, 1>>>(out);                    // slot 6
}